// round 8
// baseline (speedup 1.0000x reference)
#include <cuda_runtime.h>
#include <cuda_fp16.h>

// Shape (B=2, C=1, D=160, H=192, W=224), win=5, eps=1e-8
#define DD 160
#define HH 192
#define WW 224
#define BB 2
#define HW (HH * WW)
#define TX 32
#define TY 12
#define RR 16                    // rows per block = TY + 4
#define RCOLS 36                 // halo cols = TX + 4
#define CHUNK 40                 // z-outputs per block
#define GX (WW / TX)             // 7
#define GY (HH / TY)             // 16
#define NCZ (DD / CHUNK)         // 4
#define GZ (BB * NCZ)            // 8
#define NBLOCKS (GX * GY * GZ)   // 896
#define NT 512
#define NTOT ((double)BB * DD * HH * WW)

// dynamic smem layout (bytes)
#define OFF_RAW   0                           // uint2 [2][RR][RCOLS] = 9216
#define OFF_ZS4   9216                        // float4 [2][2][RR][TX] = 32768
#define OFF_ZS1   (9216 + 32768)              // float  [2][2][RR][TX] = 8192
#define OFF_SRED  (9216 + 32768 + 8192)       // double [16] = 128
#define OFF_LAST  (OFF_SRED + 128)
#define SMEM_BYTES (OFF_LAST + 16)

__device__ double g_partials[NBLOCKS];
__device__ unsigned int g_count = 0;

__device__ __forceinline__ unsigned pack_ij(float i, float j)
{
    __half2 h = __floats2half2_rn(i, j);
    return *reinterpret_cast<unsigned*>(&h);
}
__device__ __forceinline__ float2 unpack_ij(unsigned u)
{
    __half2 h = *reinterpret_cast<__half2*>(&u);
    return __half22float2(h);
}

__device__ __forceinline__ float ncc_cc(float4 s, float sij)
{
    const float wsz = 125.0f, inv = 1.0f / 125.0f;
    const float uI = s.x * inv, uJ = s.y * inv;
    const float cross = sij - uJ * s.x - uI * s.y + uI * uJ * wsz;
    const float Iv = s.z - 2.0f * uI * s.x + uI * uI * wsz;
    const float Jv = s.w - 2.0f * uJ * s.y + uJ * uJ * wsz;
    return (cross * cross) / (Iv * Jv + 1e-8f);
}

// ring update + zs store for one slice given 5 unpacked float2 taps
#define RINGQ(SLOT, S, T0, T1, T2, T3, T4) do {                                 \
    const float a0 = T0.x + T1.x + T2.x + T3.x + T4.x;                          \
    const float a1 = T0.y + T1.y + T2.y + T3.y + T4.y;                          \
    const float a2 = fmaf(T4.x, T4.x, fmaf(T3.x, T3.x,                          \
                     fmaf(T2.x, T2.x, fmaf(T1.x, T1.x, T0.x * T0.x))));         \
    const float a3 = fmaf(T4.y, T4.y, fmaf(T3.y, T3.y,                          \
                     fmaf(T2.y, T2.y, fmaf(T1.y, T1.y, T0.y * T0.y))));         \
    const float a4 = fmaf(T4.x, T4.y, fmaf(T3.x, T3.y,                          \
                     fmaf(T2.x, T2.y, fmaf(T1.x, T1.y, T0.x * T0.y))));         \
    SI  += a0 - r0[SLOT]; r0[SLOT] = a0;                                        \
    SJ  += a1 - r1[SLOT]; r1[SLOT] = a1;                                        \
    SII += a2 - r2[SLOT]; r2[SLOT] = a2;                                        \
    SJJ += a3 - r3[SLOT]; r3[SLOT] = a3;                                        \
    SIJ += a4 - r4[SLOT]; r4[SLOT] = a4;                                        \
    zs4[bi][S][xrow][xx] = make_float4(SI, SJ, SII, SJJ);                       \
    zs1[bi][S][xrow][xx] = SIJ;                                                 \
} while (0)

// One phase = two z-slices, one barrier. SA/SB/DOY compile-time literals.
#define PHASE(SA, SB, DOY) do {                                                 \
    /* prefetch next slice pair (zpre, zpre+1) */                               \
    float Ai0 = 0.f, Aj0 = 0.f, Bi0 = 0.f, Bj0 = 0.f;                           \
    float Ai1 = 0.f, Aj1 = 0.f, Bi1 = 0.f, Bj1 = 0.f;                           \
    {                                                                           \
        const bool zA = (zpre < DD), zB = (zpre + 1 < DD);                      \
        if (zA && ok0) { const int g = pB0 + preoff;      Ai0 = gI[g]; Aj0 = gJ[g]; } \
        if (zB && ok0) { const int g = pB0 + preoff + HW; Bi0 = gI[g]; Bj0 = gJ[g]; } \
        if (has1) {                                                             \
            if (zA && ok1) { const int g = pB1 + preoff;      Ai1 = gI[g]; Aj1 = gJ[g]; } \
            if (zB && ok1) { const int g = pB1 + preoff + HW; Bi1 = gI[g]; Bj1 = gJ[g]; } \
        }                                                                       \
    }                                                                           \
    float w0 = 0.f, w1 = 0.f, w2 = 0.f, w3 = 0.f;                               \
    if (DOY && emit_ok) {                                                       \
        const int wz = zpre - 4 + esl;                                          \
        const int wb = base + wz * HW + (y0 + g4) * WW + x0 + exx;              \
        w0 = gW[wb]; w1 = gW[wb + WW]; w2 = gW[wb + 2 * WW]; w3 = gW[wb + 3 * WW]; \
    }                                                                           \
    /* XR: both slices of pair bi, one row per warp */                          \
    {                                                                           \
        uint2 u0 = sraw[bi][xrow][xx + 0];                                      \
        uint2 u1 = sraw[bi][xrow][xx + 1];                                      \
        uint2 u2 = sraw[bi][xrow][xx + 2];                                      \
        uint2 u3 = sraw[bi][xrow][xx + 3];                                      \
        uint2 u4 = sraw[bi][xrow][xx + 4];                                      \
        float2 A0 = unpack_ij(u0.x), A1 = unpack_ij(u1.x), A2 = unpack_ij(u2.x);\
        float2 A3 = unpack_ij(u3.x), A4 = unpack_ij(u4.x);                      \
        RINGQ(SA, 0, A0, A1, A2, A3, A4);                                       \
        float2 B0 = unpack_ij(u0.y), B1 = unpack_ij(u1.y), B2 = unpack_ij(u2.y);\
        float2 B3 = unpack_ij(u3.y), B4 = unpack_ij(u4.y);                      \
        RINGQ(SB, 1, B0, B1, B2, B3, B4);                                       \
    }                                                                           \
    /* store prefetched pair */                                                 \
    sraw[bi ^ 1][row0][col0] = make_uint2(pack_ij(Ai0, Aj0), pack_ij(Bi0, Bj0));\
    if (has1)                                                                   \
        sraw[bi ^ 1][row1][col1] = make_uint2(pack_ij(Ai1, Aj1), pack_ij(Bi1, Bj1)); \
    __syncthreads();                                                            \
    /* y-emit: 4 outputs/thread from 8 rows of zs[bi] */                        \
    if (DOY && emit_ok) {                                                       \
        float4 c0 = zs4[bi][esl][g4 + 0][exx]; float p0 = zs1[bi][esl][g4 + 0][exx]; \
        float4 c1 = zs4[bi][esl][g4 + 1][exx]; float p1 = zs1[bi][esl][g4 + 1][exx]; \
        float4 c2 = zs4[bi][esl][g4 + 2][exx]; float p2 = zs1[bi][esl][g4 + 2][exx]; \
        float4 c3 = zs4[bi][esl][g4 + 3][exx]; float p3 = zs1[bi][esl][g4 + 3][exx]; \
        float4 c4 = zs4[bi][esl][g4 + 4][exx]; float p4 = zs1[bi][esl][g4 + 4][exx]; \
        float4 S; float T;                                                      \
        S.x = c0.x + c1.x + c2.x + c3.x + c4.x;                                 \
        S.y = c0.y + c1.y + c2.y + c3.y + c4.y;                                 \
        S.z = c0.z + c1.z + c2.z + c3.z + c4.z;                                 \
        S.w = c0.w + c1.w + c2.w + c3.w + c4.w;                                 \
        T   = p0 + p1 + p2 + p3 + p4;                                           \
        acc = fmaf(ncc_cc(S, T), w0, acc);                                      \
        float4 c5 = zs4[bi][esl][g4 + 5][exx]; float p5 = zs1[bi][esl][g4 + 5][exx]; \
        S.x += c5.x - c0.x; S.y += c5.y - c0.y;                                 \
        S.z += c5.z - c0.z; S.w += c5.w - c0.w; T += p5 - p0;                   \
        acc = fmaf(ncc_cc(S, T), w1, acc);                                      \
        float4 c6 = zs4[bi][esl][g4 + 6][exx]; float p6 = zs1[bi][esl][g4 + 6][exx]; \
        S.x += c6.x - c1.x; S.y += c6.y - c1.y;                                 \
        S.z += c6.z - c1.z; S.w += c6.w - c1.w; T += p6 - p1;                   \
        acc = fmaf(ncc_cc(S, T), w2, acc);                                      \
        float4 c7 = zs4[bi][esl][g4 + 7][exx]; float p7 = zs1[bi][esl][g4 + 7][exx]; \
        S.x += c7.x - c2.x; S.y += c7.y - c2.y;                                 \
        S.z += c7.z - c2.z; S.w += c7.w - c2.w; T += p7 - p2;                   \
        acc = fmaf(ncc_cc(S, T), w3, acc);                                      \
    }                                                                           \
    bi ^= 1; zpre += 2; preoff += 2 * HW;                                       \
} while (0)

__global__ __launch_bounds__(NT, 2)
void ncc_fused(const float* __restrict__ gI,
               const float* __restrict__ gJ,
               const float* __restrict__ gW,
               float* __restrict__ out)
{
    extern __shared__ unsigned char dsm[];
    uint2  (*sraw)[RR][RCOLS]   = (uint2  (*)[RR][RCOLS])(dsm + OFF_RAW);
    float4 (*zs4)[2][RR][TX]    = (float4 (*)[2][RR][TX])(dsm + OFF_ZS4);
    float  (*zs1)[2][RR][TX]    = (float  (*)[2][RR][TX])(dsm + OFF_ZS1);
    double* sred  = (double*)(dsm + OFF_SRED);
    int*    slast = (int*)(dsm + OFF_LAST);

    const int tid  = threadIdx.x;
    const int lane = tid & 31;
    const int warp = tid >> 5;
    const int x0 = blockIdx.x * TX;
    const int y0 = blockIdx.y * TY;
    const int cz = blockIdx.z % NCZ;
    const int b  = blockIdx.z / NCZ;
    const int z0 = cz * CHUNK;
    const int base = b * (DD * HW);

    // ---- raw loader mapping: 576 entries over 512 threads ----
    const int row0 = tid / RCOLS, col0 = tid - row0 * RCOLS;
    const int gy0 = y0 + row0 - 2, gx0 = x0 + col0 - 2;
    const bool ok0 = ((unsigned)gy0 < HH) && ((unsigned)gx0 < WW);
    const int pB0 = base + (ok0 ? gy0 * WW + gx0 : 0);

    const bool has1 = (tid < RR * RCOLS - NT);    // 64 extra entries
    const int e1 = tid + NT;
    const int row1 = e1 / RCOLS, col1 = e1 - row1 * RCOLS;
    const int gy1 = y0 + row1 - 2, gx1 = x0 + col1 - 2;
    const bool ok1 = ((unsigned)gy1 < HH) && ((unsigned)gx1 < WW);
    const int pB1 = base + (ok1 ? gy1 * WW + gx1 : 0);

    // ---- XR mapping: one row per warp, lane = x ----
    const int xrow = warp;          // 0..15
    const int xx   = lane;          // 0..31

    // ---- y-emit mapping: 192 threads = 2 slices x 3 row-groups x 32 cols ----
    const bool emit_ok = (tid < 192);
    const int esl = tid / 96;                    // slice of the pair
    const int eu  = tid - esl * 96;
    const int exx = eu & 31;
    const int g4  = (eu >> 5) * 4;               // output rows g4..g4+3

    // ---- z ring (static slots) + running sums ----
    float r0[5] = {0,0,0,0,0}, r1[5] = {0,0,0,0,0}, r2[5] = {0,0,0,0,0};
    float r3[5] = {0,0,0,0,0}, r4[5] = {0,0,0,0,0};
    float SI = 0.f, SJ = 0.f, SII = 0.f, SJJ = 0.f, SIJ = 0.f;
    float acc = 0.f;

    // ---- prologue: slices z0-2, z0-1 into pair 0 ----
    {
        const int zp = z0 - 2;
        const int zo = zp * HW;
        float a0i = 0.f, a0j = 0.f, b0i = 0.f, b0j = 0.f;
        float a1i = 0.f, a1j = 0.f, b1i = 0.f, b1j = 0.f;
        if (zp >= 0 && ok0)     { const int g = pB0 + zo;      a0i = gI[g]; a0j = gJ[g]; }
        if (zp + 1 >= 0 && ok0) { const int g = pB0 + zo + HW; b0i = gI[g]; b0j = gJ[g]; }
        if (has1) {
            if (zp >= 0 && ok1)     { const int g = pB1 + zo;      a1i = gI[g]; a1j = gJ[g]; }
            if (zp + 1 >= 0 && ok1) { const int g = pB1 + zo + HW; b1i = gI[g]; b1j = gJ[g]; }
        }
        sraw[0][row0][col0] = make_uint2(pack_ij(a0i, a0j), pack_ij(b0i, b0j));
        if (has1)
            sraw[0][row1][col1] = make_uint2(pack_ij(a1i, a1j), pack_ij(b1i, b1j));
        __syncthreads();
    }

    int bi = 0;
    int zpre = z0;               // phase p prefetches slices z0+2p, z0+2p+1
    int preoff = z0 * HW;

    PHASE(0, 1, false);          // XR z0-2, z0-1
    PHASE(2, 3, false);          // XR z0,   z0+1
#pragma unroll 1
    for (int g = 0; g < 2; ++g) {   // 20 emit phases (slot period 5 x parity 2)
        PHASE(4, 0, true);
        PHASE(1, 2, true);
        PHASE(3, 4, true);
        PHASE(0, 1, true);
        PHASE(2, 3, true);
        PHASE(4, 0, true);
        PHASE(1, 2, true);
        PHASE(3, 4, true);
        PHASE(0, 1, true);
        PHASE(2, 3, true);
    }

    // ---- reduction: shuffle tree (deterministic) ----
    double a = (double)acc;
#pragma unroll
    for (int off = 16; off > 0; off >>= 1)
        a += __shfl_down_sync(0xffffffffu, a, off);
    if (lane == 0) sred[warp] = a;
    __syncthreads();
    if (warp == 0) {
        double s = (lane < 16) ? sred[lane] : 0.0;
#pragma unroll
        for (int off = 8; off > 0; off >>= 1)
            s += __shfl_down_sync(0xffffffffu, s, off);
        if (lane == 0) {
            const int bidx = ((int)blockIdx.z * GY + (int)blockIdx.y) * GX + (int)blockIdx.x;
            g_partials[bidx] = s;
            __threadfence();
            const unsigned v = atomicAdd(&g_count, 1u);
            *slast = (v == NBLOCKS - 1);
        }
    }
    __syncthreads();

    // ---- last block folds all partials in fixed order ----
    if (*slast) {
        double s = 0.0;
        for (int i = tid; i < NBLOCKS; i += NT) s += g_partials[i];
#pragma unroll
        for (int off = 16; off > 0; off >>= 1)
            s += __shfl_down_sync(0xffffffffu, s, off);
        if (lane == 0) sred[warp] = s;
        __syncthreads();
        if (warp == 0) {
            double t = (lane < 16) ? sred[lane] : 0.0;
#pragma unroll
            for (int off = 8; off > 0; off >>= 1)
                t += __shfl_down_sync(0xffffffffu, t, off);
            if (lane == 0) {
                out[0] = (float)(-t / NTOT);
                g_count = 0;   // reset for next graph replay
            }
        }
    }
}

extern "C" void kernel_launch(void* const* d_in, const int* in_sizes, int n_in,
                              void* d_out, int out_size)
{
    const float* I  = (const float*)d_in[0];
    const float* J  = (const float*)d_in[1];
    const float* Wt = (const float*)d_in[2];
    float* out = (float*)d_out;

    cudaFuncSetAttribute(ncc_fused, cudaFuncAttributeMaxDynamicSharedMemorySize,
                         SMEM_BYTES);
    dim3 grid(GX, GY, GZ);
    ncc_fused<<<grid, NT, SMEM_BYTES>>>(I, J, Wt, out);
}

// round 9
// speedup vs baseline: 1.0591x; 1.0591x over previous
#include <cuda_runtime.h>

// Shape (B=2, C=1, D=160, H=192, W=224), win=5, eps=1e-8
#define DD 160
#define HH 192
#define WW 224
#define BB 2
#define HW (HH * WW)
#define TX 32
#define TY 12
#define RR 16                    // rows per block = TY + 4
#define RCOLS 36                 // halo cols = TX + 4
#define CHUNK 40                 // z-outputs per block
#define GX (WW / TX)             // 7
#define GY (HH / TY)             // 16
#define NCZ (DD / CHUNK)         // 4
#define GZ (BB * NCZ)            // 8
#define NBLOCKS (GX * GY * GZ)   // 896
#define NT 512
#define NTOT ((double)BB * DD * HH * WW)

// dynamic smem layout (bytes)
#define OFF_RAW   0                            // float4 [2][RR][RCOLS] = 18432
#define OFF_ZS4   18432                        // float4 [2][2][RR][TX] = 32768
#define OFF_ZS1   (18432 + 32768)              // float  [2][2][RR][TX] = 8192
#define OFF_SRED  (18432 + 32768 + 8192)       // double [16] = 128
#define OFF_LAST  (OFF_SRED + 128)
#define SMEM_BYTES (OFF_LAST + 16)

__device__ double g_partials[NBLOCKS];
__device__ unsigned int g_count = 0;

__device__ __forceinline__ float ncc_cc(float4 s, float sij)
{
    const float wsz = 125.0f, inv = 1.0f / 125.0f;
    const float uI = s.x * inv, uJ = s.y * inv;
    const float cross = sij - uJ * s.x - uI * s.y + uI * uJ * wsz;
    const float Iv = s.z - 2.0f * uI * s.x + uI * uI * wsz;
    const float Jv = s.w - 2.0f * uJ * s.y + uJ * uJ * wsz;
    return (cross * cross) / (Iv * Jv + 1e-8f);
}

// ring update + zs store for one slice given 5 float2 taps
#define RINGQ(SLOT, S, T0, T1, T2, T3, T4) do {                                 \
    const float a0 = T0.x + T1.x + T2.x + T3.x + T4.x;                          \
    const float a1 = T0.y + T1.y + T2.y + T3.y + T4.y;                          \
    const float a2 = fmaf(T4.x, T4.x, fmaf(T3.x, T3.x,                          \
                     fmaf(T2.x, T2.x, fmaf(T1.x, T1.x, T0.x * T0.x))));         \
    const float a3 = fmaf(T4.y, T4.y, fmaf(T3.y, T3.y,                          \
                     fmaf(T2.y, T2.y, fmaf(T1.y, T1.y, T0.y * T0.y))));         \
    const float a4 = fmaf(T4.x, T4.y, fmaf(T3.x, T3.y,                          \
                     fmaf(T2.x, T2.y, fmaf(T1.x, T1.y, T0.x * T0.y))));         \
    SI  += a0 - r0[SLOT]; r0[SLOT] = a0;                                        \
    SJ  += a1 - r1[SLOT]; r1[SLOT] = a1;                                        \
    SII += a2 - r2[SLOT]; r2[SLOT] = a2;                                        \
    SJJ += a3 - r3[SLOT]; r3[SLOT] = a3;                                        \
    SIJ += a4 - r4[SLOT]; r4[SLOT] = a4;                                        \
    zs4[bi][S][xrow][xx] = make_float4(SI, SJ, SII, SJJ);                       \
    zs1[bi][S][xrow][xx] = SIJ;                                                 \
} while (0)

// One phase = two z-slices, one barrier. SA/SB/DOY compile-time literals.
#define PHASE(SA, SB, DOY) do {                                                 \
    /* prefetch next slice pair (zpre, zpre+1) into registers */                \
    float Ai0 = 0.f, Aj0 = 0.f, Bi0 = 0.f, Bj0 = 0.f;                           \
    float Ai1 = 0.f, Aj1 = 0.f, Bi1 = 0.f, Bj1 = 0.f;                           \
    {                                                                           \
        const bool zA = (zpre < DD), zB = (zpre + 1 < DD);                      \
        if (zA && ok0) { const int g = pB0 + preoff;      Ai0 = gI[g]; Aj0 = gJ[g]; } \
        if (zB && ok0) { const int g = pB0 + preoff + HW; Bi0 = gI[g]; Bj0 = gJ[g]; } \
        if (has1) {                                                             \
            if (zA && ok1) { const int g = pB1 + preoff;      Ai1 = gI[g]; Aj1 = gJ[g]; } \
            if (zB && ok1) { const int g = pB1 + preoff + HW; Bi1 = gI[g]; Bj1 = gJ[g]; } \
        }                                                                       \
    }                                                                           \
    float w0 = 0.f, w1 = 0.f, w2 = 0.f;                                         \
    if (DOY && emit_ok) {                                                       \
        const int wb = base + (zpre - 4 + esl) * HW + (y0 + g3) * WW + x0 + exx;\
        w0 = gW[wb]; w1 = gW[wb + WW]; w2 = gW[wb + 2 * WW];                    \
    }                                                                           \
    /* XR: 5 float4 taps cover BOTH slices of pair bi */                        \
    {                                                                           \
        float4 t0 = sraw[bi][xrow][xx + 0];                                     \
        float4 t1 = sraw[bi][xrow][xx + 1];                                     \
        float4 t2 = sraw[bi][xrow][xx + 2];                                     \
        float4 t3 = sraw[bi][xrow][xx + 3];                                     \
        float4 t4 = sraw[bi][xrow][xx + 4];                                     \
        float2 A0 = make_float2(t0.x, t0.y), A1 = make_float2(t1.x, t1.y);      \
        float2 A2 = make_float2(t2.x, t2.y), A3 = make_float2(t3.x, t3.y);      \
        float2 A4 = make_float2(t4.x, t4.y);                                    \
        RINGQ(SA, 0, A0, A1, A2, A3, A4);                                       \
        float2 B0 = make_float2(t0.z, t0.w), B1 = make_float2(t1.z, t1.w);      \
        float2 B2 = make_float2(t2.z, t2.w), B3 = make_float2(t3.z, t3.w);      \
        float2 B4 = make_float2(t4.z, t4.w);                                    \
        RINGQ(SB, 1, B0, B1, B2, B3, B4);                                       \
    }                                                                           \
    /* store prefetched pair (one STS.128 per entry) */                         \
    sraw[bi ^ 1][row0][col0] = make_float4(Ai0, Aj0, Bi0, Bj0);                 \
    if (has1) sraw[bi ^ 1][row1][col1] = make_float4(Ai1, Aj1, Bi1, Bj1);       \
    __syncthreads();                                                            \
    /* y-emit: 3 outputs/thread from 7 rows of zs[bi], 8 warps wide */          \
    if (DOY && emit_ok) {                                                       \
        float4 c0 = zs4[bi][esl][g3 + 0][exx]; float p0 = zs1[bi][esl][g3 + 0][exx]; \
        float4 c1 = zs4[bi][esl][g3 + 1][exx]; float p1 = zs1[bi][esl][g3 + 1][exx]; \
        float4 c2 = zs4[bi][esl][g3 + 2][exx]; float p2 = zs1[bi][esl][g3 + 2][exx]; \
        float4 c3 = zs4[bi][esl][g3 + 3][exx]; float p3 = zs1[bi][esl][g3 + 3][exx]; \
        float4 c4 = zs4[bi][esl][g3 + 4][exx]; float p4 = zs1[bi][esl][g3 + 4][exx]; \
        float4 c5 = zs4[bi][esl][g3 + 5][exx]; float p5 = zs1[bi][esl][g3 + 5][exx]; \
        float4 c6 = zs4[bi][esl][g3 + 6][exx]; float p6 = zs1[bi][esl][g3 + 6][exx]; \
        float4 S; float T;                                                      \
        S.x = c0.x + c1.x + c2.x + c3.x + c4.x;                                 \
        S.y = c0.y + c1.y + c2.y + c3.y + c4.y;                                 \
        S.z = c0.z + c1.z + c2.z + c3.z + c4.z;                                 \
        S.w = c0.w + c1.w + c2.w + c3.w + c4.w;                                 \
        T   = p0 + p1 + p2 + p3 + p4;                                           \
        acc = fmaf(ncc_cc(S, T), w0, acc);                                      \
        S.x += c5.x - c0.x; S.y += c5.y - c0.y;                                 \
        S.z += c5.z - c0.z; S.w += c5.w - c0.w; T += p5 - p0;                   \
        acc = fmaf(ncc_cc(S, T), w1, acc);                                      \
        S.x += c6.x - c1.x; S.y += c6.y - c1.y;                                 \
        S.z += c6.z - c1.z; S.w += c6.w - c1.w; T += p6 - p1;                   \
        acc = fmaf(ncc_cc(S, T), w2, acc);                                      \
    }                                                                           \
    bi ^= 1; zpre += 2; preoff += 2 * HW;                                       \
} while (0)

__global__ __launch_bounds__(NT, 2)
void ncc_fused(const float* __restrict__ gI,
               const float* __restrict__ gJ,
               const float* __restrict__ gW,
               float* __restrict__ out)
{
    extern __shared__ unsigned char dsm[];
    float4 (*sraw)[RR][RCOLS]   = (float4 (*)[RR][RCOLS])(dsm + OFF_RAW);
    float4 (*zs4)[2][RR][TX]    = (float4 (*)[2][RR][TX])(dsm + OFF_ZS4);
    float  (*zs1)[2][RR][TX]    = (float  (*)[2][RR][TX])(dsm + OFF_ZS1);
    double* sred  = (double*)(dsm + OFF_SRED);
    int*    slast = (int*)(dsm + OFF_LAST);

    const int tid  = threadIdx.x;
    const int lane = tid & 31;
    const int warp = tid >> 5;
    const int x0 = blockIdx.x * TX;
    const int y0 = blockIdx.y * TY;
    const int cz = blockIdx.z % NCZ;
    const int b  = blockIdx.z / NCZ;
    const int z0 = cz * CHUNK;
    const int base = b * (DD * HW);

    // ---- raw loader mapping: 576 entries over 512 threads ----
    const int row0 = tid / RCOLS, col0 = tid - row0 * RCOLS;
    const int gy0 = y0 + row0 - 2, gx0 = x0 + col0 - 2;
    const bool ok0 = ((unsigned)gy0 < HH) && ((unsigned)gx0 < WW);
    const int pB0 = base + (ok0 ? gy0 * WW + gx0 : 0);

    const bool has1 = (tid < RR * RCOLS - NT);    // 64 extra entries
    const int e1 = tid + NT;
    const int row1 = e1 / RCOLS, col1 = e1 - row1 * RCOLS;
    const int gy1 = y0 + row1 - 2, gx1 = x0 + col1 - 2;
    const bool ok1 = ((unsigned)gy1 < HH) && ((unsigned)gx1 < WW);
    const int pB1 = base + (ok1 ? gy1 * WW + gx1 : 0);

    // ---- XR mapping: one row per warp, lane = x ----
    const int xrow = warp;          // 0..15
    const int xx   = lane;          // 0..31

    // ---- y-emit mapping: 256 threads = 2 slices x 4 row-groups x 32 cols ----
    const bool emit_ok = (tid < 256);
    const int esl = tid >> 7;                    // slice of the pair
    const int eu  = tid & 127;
    const int exx = eu & 31;
    const int g3  = (eu >> 5) * 3;               // output rows g3..g3+2

    // ---- z ring (static slots) + running sums ----
    float r0[5] = {0,0,0,0,0}, r1[5] = {0,0,0,0,0}, r2[5] = {0,0,0,0,0};
    float r3[5] = {0,0,0,0,0}, r4[5] = {0,0,0,0,0};
    float SI = 0.f, SJ = 0.f, SII = 0.f, SJJ = 0.f, SIJ = 0.f;
    float acc = 0.f;

    // ---- prologue: slices z0-2, z0-1 into pair 0 ----
    {
        const int zp = z0 - 2;
        const int zo = zp * HW;
        float a0i = 0.f, a0j = 0.f, b0i = 0.f, b0j = 0.f;
        float a1i = 0.f, a1j = 0.f, b1i = 0.f, b1j = 0.f;
        if (zp >= 0 && ok0)     { const int g = pB0 + zo;      a0i = gI[g]; a0j = gJ[g]; }
        if (zp + 1 >= 0 && ok0) { const int g = pB0 + zo + HW; b0i = gI[g]; b0j = gJ[g]; }
        if (has1) {
            if (zp >= 0 && ok1)     { const int g = pB1 + zo;      a1i = gI[g]; a1j = gJ[g]; }
            if (zp + 1 >= 0 && ok1) { const int g = pB1 + zo + HW; b1i = gI[g]; b1j = gJ[g]; }
        }
        sraw[0][row0][col0] = make_float4(a0i, a0j, b0i, b0j);
        if (has1) sraw[0][row1][col1] = make_float4(a1i, a1j, b1i, b1j);
        __syncthreads();
    }

    int bi = 0;
    int zpre = z0;               // phase p prefetches slices z0+2p, z0+2p+1
    int preoff = z0 * HW;

    PHASE(0, 1, false);          // XR z0-2, z0-1
    PHASE(2, 3, false);          // XR z0,   z0+1
#pragma unroll 1
    for (int g = 0; g < 2; ++g) {   // 20 emit phases (slot period 5 x parity 2)
        PHASE(4, 0, true);
        PHASE(1, 2, true);
        PHASE(3, 4, true);
        PHASE(0, 1, true);
        PHASE(2, 3, true);
        PHASE(4, 0, true);
        PHASE(1, 2, true);
        PHASE(3, 4, true);
        PHASE(0, 1, true);
        PHASE(2, 3, true);
    }

    // ---- reduction: shuffle tree (deterministic) ----
    double a = (double)acc;
#pragma unroll
    for (int off = 16; off > 0; off >>= 1)
        a += __shfl_down_sync(0xffffffffu, a, off);
    if (lane == 0) sred[warp] = a;
    __syncthreads();
    if (warp == 0) {
        double s = (lane < 16) ? sred[lane] : 0.0;
#pragma unroll
        for (int off = 8; off > 0; off >>= 1)
            s += __shfl_down_sync(0xffffffffu, s, off);
        if (lane == 0) {
            const int bidx = ((int)blockIdx.z * GY + (int)blockIdx.y) * GX + (int)blockIdx.x;
            g_partials[bidx] = s;
            __threadfence();
            const unsigned v = atomicAdd(&g_count, 1u);
            *slast = (v == NBLOCKS - 1);
        }
    }
    __syncthreads();

    // ---- last block folds all partials in fixed order ----
    if (*slast) {
        double s = 0.0;
        for (int i = tid; i < NBLOCKS; i += NT) s += g_partials[i];
#pragma unroll
        for (int off = 16; off > 0; off >>= 1)
            s += __shfl_down_sync(0xffffffffu, s, off);
        if (lane == 0) sred[warp] = s;
        __syncthreads();
        if (warp == 0) {
            double t = (lane < 16) ? sred[lane] : 0.0;
#pragma unroll
            for (int off = 8; off > 0; off >>= 1)
                t += __shfl_down_sync(0xffffffffu, t, off);
            if (lane == 0) {
                out[0] = (float)(-t / NTOT);
                g_count = 0;   // reset for next graph replay
            }
        }
    }
}

extern "C" void kernel_launch(void* const* d_in, const int* in_sizes, int n_in,
                              void* d_out, int out_size)
{
    const float* I  = (const float*)d_in[0];
    const float* J  = (const float*)d_in[1];
    const float* Wt = (const float*)d_in[2];
    float* out = (float*)d_out;

    cudaFuncSetAttribute(ncc_fused, cudaFuncAttributeMaxDynamicSharedMemorySize,
                         SMEM_BYTES);
    dim3 grid(GX, GY, GZ);
    ncc_fused<<<grid, NT, SMEM_BYTES>>>(I, J, Wt, out);
}

// round 10
// speedup vs baseline: 1.5425x; 1.4564x over previous
#include <cuda_runtime.h>

// Shape (B=2, C=1, D=160, H=192, W=224), win=5, eps=1e-8
#define DD 160
#define HH 192
#define WW 224
#define BB 2
#define HW (HH * WW)
#define TX 32
#define TY 12
#define RR 16                    // rows per block = TY + 4
#define RCOLS 36                 // halo cols = TX + 4
#define GX (WW / TX)             // 7
#define GY (HH / TY)             // 16
#define NCOLS (BB * GX * GY)     // 224 (x,y,b) columns
#define NBLOCKS 888              // == 296 * 3 : exact multiple of concurrency
#define NT 512
#define NTOT ((double)BB * DD * HH * WW)

// dynamic smem layout (bytes)
#define OFF_RAW   0                            // float2 [2][2][RR][RCOLS] = 18432
#define OFF_ZS4   18432                        // float4 [2][2][RR][TX]   = 32768
#define OFF_ZS1   (18432 + 32768)              // float  [2][2][RR][TX]   = 8192
#define OFF_SRED  (18432 + 32768 + 8192)       // double [16]             = 128
#define OFF_LAST  (OFF_SRED + 128)             // int
#define SMEM_BYTES (OFF_LAST + 16)

__device__ double g_partials[NBLOCKS];
__device__ unsigned int g_count = 0;

__device__ __forceinline__ float ncc_cc(float4 s, float sij)
{
    const float wsz = 125.0f, inv = 1.0f / 125.0f;
    const float uI = s.x * inv, uJ = s.y * inv;
    const float cross = sij - uJ * s.x - uI * s.y + uI * uJ * wsz;
    const float Iv = s.z - 2.0f * uI * s.x + uI * uI * wsz;
    const float Jv = s.w - 2.0f * uJ * s.y + uJ * uJ * wsz;
    return (cross * cross) / (Iv * Jv + 1e-8f);
}

// x-box sums + z-ring update for one slice S (0/1) of current pair bi.
#define XR(SLOT, S) do {                                                        \
    float2 v0 = sraw[bi][S][xr][xx + 0];                                        \
    float2 v1 = sraw[bi][S][xr][xx + 1];                                        \
    float2 v2 = sraw[bi][S][xr][xx + 2];                                        \
    float2 v3 = sraw[bi][S][xr][xx + 3];                                        \
    float2 v4 = sraw[bi][S][xr][xx + 4];                                        \
    const float a0 = v0.x + v1.x + v2.x + v3.x + v4.x;                          \
    const float a1 = v0.y + v1.y + v2.y + v3.y + v4.y;                          \
    const float a2 = fmaf(v4.x, v4.x, fmaf(v3.x, v3.x,                          \
                     fmaf(v2.x, v2.x, fmaf(v1.x, v1.x, v0.x * v0.x))));         \
    const float a3 = fmaf(v4.y, v4.y, fmaf(v3.y, v3.y,                          \
                     fmaf(v2.y, v2.y, fmaf(v1.y, v1.y, v0.y * v0.y))));         \
    const float a4 = fmaf(v4.x, v4.y, fmaf(v3.x, v3.y,                          \
                     fmaf(v2.x, v2.y, fmaf(v1.x, v1.y, v0.x * v0.y))));         \
    SI  += a0 - r0[SLOT]; r0[SLOT] = a0;                                        \
    SJ  += a1 - r1[SLOT]; r1[SLOT] = a1;                                        \
    SII += a2 - r2[SLOT]; r2[SLOT] = a2;                                        \
    SJJ += a3 - r3[SLOT]; r3[SLOT] = a3;                                        \
    SIJ += a4 - r4[SLOT]; r4[SLOT] = a4;                                        \
    zs4[bi][S][xr][xx] = make_float4(SI, SJ, SII, SJJ);                         \
    zs1[bi][S][xr][xx] = SIJ;                                                   \
} while (0)

// One phase = two z-slices, one barrier. SA/SB/DOY compile-time literals.
#define PHASE(SA, SB, DOY) do {                                                 \
    float Ai0 = 0.f, Aj0 = 0.f, Ai1 = 0.f, Aj1 = 0.f;                           \
    float Bi0 = 0.f, Bj0 = 0.f, Bi1 = 0.f, Bj1 = 0.f;                           \
    {                                                                           \
        const bool zA = (zpre < DD), zB = (zpre + 1 < DD);                      \
        if (zA && ok0) { const int g = pB0 + preoff;      Ai0 = gI[g]; Aj0 = gJ[g]; } \
        if (zB && ok0) { const int g = pB0 + preoff + HW; Bi0 = gI[g]; Bj0 = gJ[g]; } \
        if (has1) {                                                             \
            if (zA && ok1) { const int g = pB1 + preoff;      Ai1 = gI[g]; Aj1 = gJ[g]; } \
            if (zB && ok1) { const int g = pB1 + preoff + HW; Bi1 = gI[g]; Bj1 = gJ[g]; } \
        }                                                                       \
    }                                                                           \
    float w0 = 0.f, w1 = 0.f;                                                   \
    if (DOY && emit_ok) { w0 = gW[woff]; w1 = gW[woff + WW]; }                  \
    XR(SA, 0);                                                                  \
    XR(SB, 1);                                                                  \
    {                                                                           \
        const int nb = bi ^ 1;                                                  \
        sraw[nb][0][row0][col0] = make_float2(Ai0, Aj0);                        \
        sraw[nb][1][row0][col0] = make_float2(Bi0, Bj0);                        \
        if (has1) {                                                             \
            sraw[nb][0][row1][col1] = make_float2(Ai1, Aj1);                    \
            sraw[nb][1][row1][col1] = make_float2(Bi1, Bj1);                    \
        }                                                                       \
    }                                                                           \
    __syncthreads();                                                            \
    if (DOY && emit_ok) {                                                       \
        float4 sA = make_float4(0.f, 0.f, 0.f, 0.f);                            \
        float4 sB = make_float4(0.f, 0.f, 0.f, 0.f);                            \
        float sA1 = 0.f, sB1 = 0.f;                                             \
        _Pragma("unroll")                                                       \
        for (int j = 0; j < 6; ++j) {                                           \
            float4 v = zs4[bi][esl][yb + j][exx];                               \
            float  u = zs1[bi][esl][yb + j][exx];                               \
            if (j < 5) { sA.x += v.x; sA.y += v.y; sA.z += v.z; sA.w += v.w;    \
                         sA1 += u; }                                            \
            if (j > 0) { sB.x += v.x; sB.y += v.y; sB.z += v.z; sB.w += v.w;    \
                         sB1 += u; }                                            \
        }                                                                       \
        acc = fmaf(ncc_cc(sA, sA1), w0, acc);                                   \
        acc = fmaf(ncc_cc(sB, sB1), w1, acc);                                   \
        woff += 2 * HW;                                                         \
    }                                                                           \
    bi ^= 1; zpre += 2; preoff += 2 * HW;                                       \
} while (0)

__global__ __launch_bounds__(NT, 2)
void ncc_fused(const float* __restrict__ gI,
               const float* __restrict__ gJ,
               const float* __restrict__ gW,
               float* __restrict__ out)
{
    extern __shared__ unsigned char dsm[];
    float2 (*sraw)[2][RR][RCOLS] = (float2 (*)[2][RR][RCOLS])(dsm + OFF_RAW);
    float4 (*zs4)[2][RR][TX]     = (float4 (*)[2][RR][TX])(dsm + OFF_ZS4);
    float  (*zs1)[2][RR][TX]     = (float  (*)[2][RR][TX])(dsm + OFF_ZS1);
    double* sred  = (double*)(dsm + OFF_SRED);
    int*    slast = (int*)(dsm + OFF_LAST);

    const int tid  = threadIdx.x;
    const int lane = tid & 31;
    const int warp = tid >> 5;

    // ---- block schedule decode: 888 blocks over 224 columns ----
    // blocks 0..23  : 8 special columns x 3 chunks, z0 = {0,54,108}, len = {54,54,52}
    // blocks 24..887: 216 regular columns x 4 chunks of len 40
    const int bid = blockIdx.x;
    int c, z0, npairs;
    if (bid < 24) {
        c = bid / 3;
        const int ci = bid - c * 3;
        z0 = ci * 54;                    // 0, 54, 108
        npairs = (ci == 2) ? 26 : 27;    // len/2 : 54,54,52
    } else {
        const int q = bid - 24;
        c = 8 + (q >> 2);
        const int ci = q & 3;
        z0 = ci * 40;
        npairs = 20;
    }
    const int b  = c / (GX * GY);
    const int rr = c - b * (GX * GY);
    const int yt = rr / GX;
    const int xt = rr - yt * GX;
    const int x0 = xt * TX;
    const int y0 = yt * TY;
    const int base = b * (DD * HW);

    // ---- raw loader mapping: 576 entries over 512 threads ----
    const int row0 = tid / RCOLS, col0 = tid - row0 * RCOLS;
    const int gy0 = y0 + row0 - 2, gx0 = x0 + col0 - 2;
    const bool ok0 = ((unsigned)gy0 < HH) && ((unsigned)gx0 < WW);
    const int pB0 = base + (ok0 ? gy0 * WW + gx0 : 0);

    const bool has1 = (tid < RR * RCOLS - NT);    // 64 extra entries
    const int e1 = tid + NT;
    const int row1 = e1 / RCOLS, col1 = e1 - row1 * RCOLS;
    const int gy1 = y0 + row1 - 2, gx1 = x0 + col1 - 2;
    const bool ok1 = ((unsigned)gy1 < HH) && ((unsigned)gx1 < WW);
    const int pB1 = base + (ok1 ? gy1 * WW + gx1 : 0);

    // ---- xsum entry: one (row, x) per thread ----
    const int xr = warp;            // 0..15
    const int xx = lane;            // 0..31

    // ---- y-emit mapping: 384 threads, 2 slices x 192 ----
    const bool emit_ok = (tid < 384);
    const int esl = tid / 192;                 // slice of the pair
    const int eu  = tid - esl * 192;
    const int exx = eu & 31;
    const int yb  = (eu >> 5) * 2;             // 0,2,..,10
    int woff = base + (z0 + esl) * HW + (y0 + yb) * WW + (x0 + exx);

    // ---- z ring (static slots) + running sums ----
    float r0[5] = {0,0,0,0,0}, r1[5] = {0,0,0,0,0}, r2[5] = {0,0,0,0,0};
    float r3[5] = {0,0,0,0,0}, r4[5] = {0,0,0,0,0};
    float SI = 0.f, SJ = 0.f, SII = 0.f, SJJ = 0.f, SIJ = 0.f;
    float acc = 0.f;

    // ---- prologue: slices z0-2, z0-1 into pair 0 ----
    {
        const int zp = z0 - 2;
        const int zo = zp * HW;
        float a0i = 0.f, a0j = 0.f, b0i = 0.f, b0j = 0.f;
        float a1i = 0.f, a1j = 0.f, b1i = 0.f, b1j = 0.f;
        if (zp >= 0 && ok0)     { const int g = pB0 + zo;      a0i = gI[g]; a0j = gJ[g]; }
        if (zp + 1 >= 0 && ok0) { const int g = pB0 + zo + HW; b0i = gI[g]; b0j = gJ[g]; }
        if (has1) {
            if (zp >= 0 && ok1)     { const int g = pB1 + zo;      a1i = gI[g]; a1j = gJ[g]; }
            if (zp + 1 >= 0 && ok1) { const int g = pB1 + zo + HW; b1i = gI[g]; b1j = gJ[g]; }
        }
        sraw[0][0][col0 ? row0 : row0][col0] = make_float2(a0i, a0j);  // [0][0][row0][col0]
        sraw[0][0][row0][col0] = make_float2(a0i, a0j);
        sraw[0][1][row0][col0] = make_float2(b0i, b0j);
        if (has1) {
            sraw[0][0][row1][col1] = make_float2(a1i, a1j);
            sraw[0][1][row1][col1] = make_float2(b1i, b1j);
        }
        __syncthreads();
    }

    int bi = 0;
    int zpre = z0;               // phase p prefetches slices z0+2p, z0+2p+1
    int preoff = z0 * HW;

    PHASE(0, 1, false);          // XR z0-2, z0-1
    PHASE(2, 3, false);          // XR z0,   z0+1

    // ---- main: npairs emit phases, slot cycle period 5 ----
    int k5 = 0;
#pragma unroll 1
    for (int j = 0; j < npairs; ++j) {
        switch (k5) {
            case 0:  PHASE(4, 0, true); break;
            case 1:  PHASE(1, 2, true); break;
            case 2:  PHASE(3, 4, true); break;
            case 3:  PHASE(0, 1, true); break;
            default: PHASE(2, 3, true); break;
        }
        k5 = (k5 == 4) ? 0 : k5 + 1;
    }

    // ---- reduction: shuffle tree (deterministic) ----
    double a = (double)acc;
#pragma unroll
    for (int off = 16; off > 0; off >>= 1)
        a += __shfl_down_sync(0xffffffffu, a, off);
    if (lane == 0) sred[warp] = a;
    __syncthreads();
    if (warp == 0) {
        double s = (lane < 16) ? sred[lane] : 0.0;
#pragma unroll
        for (int off = 8; off > 0; off >>= 1)
            s += __shfl_down_sync(0xffffffffu, s, off);
        if (lane == 0) {
            g_partials[bid] = s;
            __threadfence();
            const unsigned v = atomicAdd(&g_count, 1u);
            *slast = (v == NBLOCKS - 1);
        }
    }
    __syncthreads();

    // ---- last block folds all partials in fixed order ----
    if (*slast) {
        double s = 0.0;
        for (int i = tid; i < NBLOCKS; i += NT) s += g_partials[i];
#pragma unroll
        for (int off = 16; off > 0; off >>= 1)
            s += __shfl_down_sync(0xffffffffu, s, off);
        if (lane == 0) sred[warp] = s;
        __syncthreads();
        if (warp == 0) {
            double t = (lane < 16) ? sred[lane] : 0.0;
#pragma unroll
            for (int off = 8; off > 0; off >>= 1)
                t += __shfl_down_sync(0xffffffffu, t, off);
            if (lane == 0) {
                out[0] = (float)(-t / NTOT);
                g_count = 0;   // reset for next graph replay
            }
        }
    }
}

extern "C" void kernel_launch(void* const* d_in, const int* in_sizes, int n_in,
                              void* d_out, int out_size)
{
    const float* I  = (const float*)d_in[0];
    const float* J  = (const float*)d_in[1];
    const float* Wt = (const float*)d_in[2];
    float* out = (float*)d_out;

    cudaFuncSetAttribute(ncc_fused, cudaFuncAttributeMaxDynamicSharedMemorySize,
                         SMEM_BYTES);
    ncc_fused<<<NBLOCKS, NT, SMEM_BYTES>>>(I, J, Wt, out);
}

// round 11
// speedup vs baseline: 1.5918x; 1.0320x over previous
#include <cuda_runtime.h>

// Shape (B=2, C=1, D=160, H=192, W=224), win=5, eps=1e-8
#define DD 160
#define HH 192
#define WW 224
#define BB 2
#define HW (HH * WW)
#define TX 32
#define TY 12
#define RR 16                    // rows per block = TY + 4
#define RCOLS 36                 // halo cols = TX + 4
#define GX (WW / TX)             // 7
#define GY (HH / TY)             // 16
#define NBLOCKS 888              // == 296 * 3 : exact multiple of chip concurrency
#define NT 512
#define NTOT ((double)BB * DD * HH * WW)

// dynamic smem layout (bytes)
#define OFF_RAW   0                            // float2 [2][2][RR][RCOLS] = 18432
#define OFF_ZS4   18432                        // float4 [2][2][RR][TX]   = 32768
#define OFF_ZS1   (18432 + 32768)              // float  [2][2][RR][TX]   = 8192
#define OFF_SRED  (18432 + 32768 + 8192)       // double [16]             = 128
#define OFF_LAST  (OFF_SRED + 128)             // int
#define SMEM_BYTES (OFF_LAST + 16)

__device__ double g_partials[NBLOCKS];
__device__ unsigned int g_count = 0;

__device__ __forceinline__ float ncc_cc(float4 s, float sij)
{
    const float wsz = 125.0f, inv = 1.0f / 125.0f;
    const float uI = s.x * inv, uJ = s.y * inv;
    const float cross = sij - uJ * s.x - uI * s.y + uI * uJ * wsz;
    const float Iv = s.z - 2.0f * uI * s.x + uI * uI * wsz;
    const float Jv = s.w - 2.0f * uJ * s.y + uJ * uJ * wsz;
    return (cross * cross) / (Iv * Jv + 1e-8f);
}

// x-box sums + z-ring update for one slice S (0/1) of current pair bi.
#define XR(SLOT, S) do {                                                        \
    float2 v0 = sraw[bi][S][xr][xx + 0];                                        \
    float2 v1 = sraw[bi][S][xr][xx + 1];                                        \
    float2 v2 = sraw[bi][S][xr][xx + 2];                                        \
    float2 v3 = sraw[bi][S][xr][xx + 3];                                        \
    float2 v4 = sraw[bi][S][xr][xx + 4];                                        \
    const float a0 = v0.x + v1.x + v2.x + v3.x + v4.x;                          \
    const float a1 = v0.y + v1.y + v2.y + v3.y + v4.y;                          \
    const float a2 = fmaf(v4.x, v4.x, fmaf(v3.x, v3.x,                          \
                     fmaf(v2.x, v2.x, fmaf(v1.x, v1.x, v0.x * v0.x))));         \
    const float a3 = fmaf(v4.y, v4.y, fmaf(v3.y, v3.y,                          \
                     fmaf(v2.y, v2.y, fmaf(v1.y, v1.y, v0.y * v0.y))));         \
    const float a4 = fmaf(v4.x, v4.y, fmaf(v3.x, v3.y,                          \
                     fmaf(v2.x, v2.y, fmaf(v1.x, v1.y, v0.x * v0.y))));         \
    SI  += a0 - r0[SLOT]; r0[SLOT] = a0;                                        \
    SJ  += a1 - r1[SLOT]; r1[SLOT] = a1;                                        \
    SII += a2 - r2[SLOT]; r2[SLOT] = a2;                                        \
    SJJ += a3 - r3[SLOT]; r3[SLOT] = a3;                                        \
    SIJ += a4 - r4[SLOT]; r4[SLOT] = a4;                                        \
    zs4[bi][S][xr][xx] = make_float4(SI, SJ, SII, SJJ);                         \
    zs1[bi][S][xr][xx] = SIJ;                                                   \
} while (0)

// One phase = two z-slices, one barrier. SA/SB/DOY compile-time literals.
#define PHASE(SA, SB, DOY) do {                                                 \
    float Ai0 = 0.f, Aj0 = 0.f, Ai1 = 0.f, Aj1 = 0.f;                           \
    float Bi0 = 0.f, Bj0 = 0.f, Bi1 = 0.f, Bj1 = 0.f;                           \
    {                                                                           \
        const bool zA = (zpre < DD), zB = (zpre + 1 < DD);                      \
        if (zA && ok0) { const int g = pB0 + preoff;      Ai0 = gI[g]; Aj0 = gJ[g]; } \
        if (zB && ok0) { const int g = pB0 + preoff + HW; Bi0 = gI[g]; Bj0 = gJ[g]; } \
        if (has1) {                                                             \
            if (zA && ok1) { const int g = pB1 + preoff;      Ai1 = gI[g]; Aj1 = gJ[g]; } \
            if (zB && ok1) { const int g = pB1 + preoff + HW; Bi1 = gI[g]; Bj1 = gJ[g]; } \
        }                                                                       \
    }                                                                           \
    float w0 = 0.f, w1 = 0.f;                                                   \
    if (DOY && emit_ok) { w0 = gW[woff]; w1 = gW[woff + WW]; }                  \
    XR(SA, 0);                                                                  \
    XR(SB, 1);                                                                  \
    {                                                                           \
        const int nb = bi ^ 1;                                                  \
        sraw[nb][0][row0][col0] = make_float2(Ai0, Aj0);                        \
        sraw[nb][1][row0][col0] = make_float2(Bi0, Bj0);                        \
        if (has1) {                                                             \
            sraw[nb][0][row1][col1] = make_float2(Ai1, Aj1);                    \
            sraw[nb][1][row1][col1] = make_float2(Bi1, Bj1);                    \
        }                                                                       \
    }                                                                           \
    __syncthreads();                                                            \
    if (DOY && emit_ok) {                                                       \
        float4 sA = make_float4(0.f, 0.f, 0.f, 0.f);                            \
        float4 sB = make_float4(0.f, 0.f, 0.f, 0.f);                            \
        float sA1 = 0.f, sB1 = 0.f;                                             \
        _Pragma("unroll")                                                       \
        for (int j = 0; j < 6; ++j) {                                           \
            float4 v = zs4[bi][esl][yb + j][exx];                               \
            float  u = zs1[bi][esl][yb + j][exx];                               \
            if (j < 5) { sA.x += v.x; sA.y += v.y; sA.z += v.z; sA.w += v.w;    \
                         sA1 += u; }                                            \
            if (j > 0) { sB.x += v.x; sB.y += v.y; sB.z += v.z; sB.w += v.w;    \
                         sB1 += u; }                                            \
        }                                                                       \
        acc = fmaf(ncc_cc(sA, sA1), w0, acc);                                   \
        acc = fmaf(ncc_cc(sB, sB1), w1, acc);                                   \
        woff += 2 * HW;                                                         \
    }                                                                           \
    bi ^= 1; zpre += 2; preoff += 2 * HW;                                       \
} while (0)

__global__ __launch_bounds__(NT, 2)
void ncc_fused(const float* __restrict__ gI,
               const float* __restrict__ gJ,
               const float* __restrict__ gW,
               float* __restrict__ out)
{
    extern __shared__ unsigned char dsm[];
    float2 (*sraw)[2][RR][RCOLS] = (float2 (*)[2][RR][RCOLS])(dsm + OFF_RAW);
    float4 (*zs4)[2][RR][TX]     = (float4 (*)[2][RR][TX])(dsm + OFF_ZS4);
    float  (*zs1)[2][RR][TX]     = (float  (*)[2][RR][TX])(dsm + OFF_ZS1);
    double* sred  = (double*)(dsm + OFF_SRED);
    int*    slast = (int*)(dsm + OFF_LAST);

    const int tid  = threadIdx.x;
    const int lane = tid & 31;
    const int warp = tid >> 5;

    // ---- block schedule decode: 888 blocks over 224 (x,y,b) columns ----
    // blocks 0..23  : 8 special columns x 3 chunks, z0={0,60,110}, len={60,50,50}
    //                 (longest first -> LPT under in-order wave-1 issue)
    // blocks 24..887: 216 regular columns x 4 chunks of len 40
    const int bid = blockIdx.x;
    int c, z0, ngrp;                      // ngrp = npairs/5
    if (bid < 24) {
        c = bid / 3;
        const int ci = bid - c * 3;
        z0   = (ci == 0) ? 0 : (ci == 1 ? 60 : 110);
        ngrp = (ci == 0) ? 6 : 5;         // 30 / 25 / 25 pairs
    } else {
        const int q = bid - 24;
        c = 8 + (q >> 2);
        const int ci = q & 3;
        z0 = ci * 40;
        ngrp = 4;                         // 20 pairs
    }
    const int b  = c / (GX * GY);
    const int rr = c - b * (GX * GY);
    const int yt = rr / GX;
    const int xt = rr - yt * GX;
    const int x0 = xt * TX;
    const int y0 = yt * TY;
    const int base = b * (DD * HW);

    // ---- raw loader mapping: 576 entries over 512 threads ----
    const int row0 = tid / RCOLS, col0 = tid - row0 * RCOLS;
    const int gy0 = y0 + row0 - 2, gx0 = x0 + col0 - 2;
    const bool ok0 = ((unsigned)gy0 < HH) && ((unsigned)gx0 < WW);
    const int pB0 = base + (ok0 ? gy0 * WW + gx0 : 0);

    const bool has1 = (tid < RR * RCOLS - NT);    // 64 extra entries
    const int e1 = tid + NT;
    const int row1 = e1 / RCOLS, col1 = e1 - row1 * RCOLS;
    const int gy1 = y0 + row1 - 2, gx1 = x0 + col1 - 2;
    const bool ok1 = ((unsigned)gy1 < HH) && ((unsigned)gx1 < WW);
    const int pB1 = base + (ok1 ? gy1 * WW + gx1 : 0);

    // ---- xsum entry: one (row, x) per thread ----
    const int xr = warp;            // 0..15
    const int xx = lane;            // 0..31

    // ---- y-emit mapping: 384 threads, 2 slices x 192 ----
    const bool emit_ok = (tid < 384);
    const int esl = tid / 192;                 // slice of the pair
    const int eu  = tid - esl * 192;
    const int exx = eu & 31;
    const int yb  = (eu >> 5) * 2;             // 0,2,..,10
    int woff = base + (z0 + esl) * HW + (y0 + yb) * WW + (x0 + exx);

    // ---- z ring (static slots) + running sums ----
    float r0[5] = {0,0,0,0,0}, r1[5] = {0,0,0,0,0}, r2[5] = {0,0,0,0,0};
    float r3[5] = {0,0,0,0,0}, r4[5] = {0,0,0,0,0};
    float SI = 0.f, SJ = 0.f, SII = 0.f, SJJ = 0.f, SIJ = 0.f;
    float acc = 0.f;

    // ---- prologue: slices z0-2, z0-1 into pair 0 ----
    {
        const int zp = z0 - 2;
        const int zo = zp * HW;
        float a0i = 0.f, a0j = 0.f, b0i = 0.f, b0j = 0.f;
        float a1i = 0.f, a1j = 0.f, b1i = 0.f, b1j = 0.f;
        if (zp >= 0 && ok0)     { const int g = pB0 + zo;      a0i = gI[g]; a0j = gJ[g]; }
        if (zp + 1 >= 0 && ok0) { const int g = pB0 + zo + HW; b0i = gI[g]; b0j = gJ[g]; }
        if (has1) {
            if (zp >= 0 && ok1)     { const int g = pB1 + zo;      a1i = gI[g]; a1j = gJ[g]; }
            if (zp + 1 >= 0 && ok1) { const int g = pB1 + zo + HW; b1i = gI[g]; b1j = gJ[g]; }
        }
        sraw[0][0][row0][col0] = make_float2(a0i, a0j);
        sraw[0][1][row0][col0] = make_float2(b0i, b0j);
        if (has1) {
            sraw[0][0][row1][col1] = make_float2(a1i, a1j);
            sraw[0][1][row1][col1] = make_float2(b1i, b1j);
        }
        __syncthreads();
    }

    int bi = 0;
    int zpre = z0;               // phase p prefetches slices z0+2p, z0+2p+1
    int preoff = z0 * HW;

    PHASE(0, 1, false);          // XR z0-2, z0-1
    PHASE(2, 3, false);          // XR z0,   z0+1

    // ---- main: ngrp statically-unrolled 5-phase groups (period = 10 slices) ----
#pragma unroll 1
    for (int g = 0; g < ngrp; ++g) {
        PHASE(4, 0, true);
        PHASE(1, 2, true);
        PHASE(3, 4, true);
        PHASE(0, 1, true);
        PHASE(2, 3, true);
    }

    // ---- reduction: shuffle tree (deterministic) ----
    double a = (double)acc;
#pragma unroll
    for (int off = 16; off > 0; off >>= 1)
        a += __shfl_down_sync(0xffffffffu, a, off);
    if (lane == 0) sred[warp] = a;
    __syncthreads();
    if (warp == 0) {
        double s = (lane < 16) ? sred[lane] : 0.0;
#pragma unroll
        for (int off = 8; off > 0; off >>= 1)
            s += __shfl_down_sync(0xffffffffu, s, off);
        if (lane == 0) {
            g_partials[bid] = s;
            __threadfence();
            const unsigned v = atomicAdd(&g_count, 1u);
            *slast = (v == NBLOCKS - 1);
        }
    }
    __syncthreads();

    // ---- last block folds all partials in fixed order ----
    if (*slast) {
        double s = 0.0;
        for (int i = tid; i < NBLOCKS; i += NT) s += g_partials[i];
#pragma unroll
        for (int off = 16; off > 0; off >>= 1)
            s += __shfl_down_sync(0xffffffffu, s, off);
        if (lane == 0) sred[warp] = s;
        __syncthreads();
        if (warp == 0) {
            double t = (lane < 16) ? sred[lane] : 0.0;
#pragma unroll
            for (int off = 8; off > 0; off >>= 1)
                t += __shfl_down_sync(0xffffffffu, t, off);
            if (lane == 0) {
                out[0] = (float)(-t / NTOT);
                g_count = 0;   // reset for next graph replay
            }
        }
    }
}

extern "C" void kernel_launch(void* const* d_in, const int* in_sizes, int n_in,
                              void* d_out, int out_size)
{
    const float* I  = (const float*)d_in[0];
    const float* J  = (const float*)d_in[1];
    const float* Wt = (const float*)d_in[2];
    float* out = (float*)d_out;

    cudaFuncSetAttribute(ncc_fused, cudaFuncAttributeMaxDynamicSharedMemorySize,
                         SMEM_BYTES);
    ncc_fused<<<NBLOCKS, NT, SMEM_BYTES>>>(I, J, Wt, out);
}

// round 12
// speedup vs baseline: 1.7298x; 1.0867x over previous
#include <cuda_runtime.h>

// Shape (B=2, C=1, D=160, H=192, W=224), win=5, eps=1e-8
#define DD 160
#define HH 192
#define WW 224
#define BB 2
#define HW (HH * WW)
#define TX 32
#define TY 12
#define RR 16                    // rows per block = TY + 4
#define RCOLS 36                 // halo cols = TX + 4
#define GX (WW / TX)             // 7
#define GY (HH / TY)             // 16
#define NBLOCKS 888              // == 296 * 3 : exact multiple of chip concurrency
#define NT 512
#define NTOT ((double)BB * DD * HH * WW)

// dynamic smem layout (bytes)
#define RAW_PAIR_BYTES 9216                    // float2 [2][RR][RCOLS]
#define RAW_SLICE_BYTES 4608                   // float2 [RR][RCOLS]
#define OFF_RAW   0                            // float2 [2][2][RR][RCOLS] = 18432
#define OFF_ZS4   18432                        // float4 [2][2][RR][TX]   = 32768
#define OFF_ZS1   (18432 + 32768)              // float  [2][2][RR][TX]   = 8192
#define OFF_SRED  (18432 + 32768 + 8192)       // double [16]             = 128
#define OFF_LAST  (OFF_SRED + 128)             // int
#define SMEM_BYTES (OFF_LAST + 16)

__device__ double g_partials[NBLOCKS];
__device__ unsigned int g_count = 0;

// 4-byte async copy global->shared with zero-fill when pred is false
__device__ __forceinline__ void cpa4(unsigned dst, const float* src, bool pred)
{
    const int sz = pred ? 4 : 0;
    asm volatile("cp.async.ca.shared.global [%0], [%1], 4, %2;"
                 :: "r"(dst), "l"(src), "r"(sz) : "memory");
}
__device__ __forceinline__ void cpa_wait_all()
{
    asm volatile("cp.async.wait_all;" ::: "memory");
}

__device__ __forceinline__ float ncc_cc(float4 s, float sij)
{
    const float wsz = 125.0f, inv = 1.0f / 125.0f;
    const float uI = s.x * inv, uJ = s.y * inv;
    const float cross = sij - uJ * s.x - uI * s.y + uI * uJ * wsz;
    const float Iv = s.z - 2.0f * uI * s.x + uI * uI * wsz;
    const float Jv = s.w - 2.0f * uJ * s.y + uJ * uJ * wsz;
    return __fdividef(cross * cross, Iv * Jv + 1e-8f);
}

// x-box sums + z-ring update for one slice S (0/1) of current pair bi.
#define XR(SLOT, S) do {                                                        \
    float2 v0 = sraw[bi][S][xr][xx + 0];                                        \
    float2 v1 = sraw[bi][S][xr][xx + 1];                                        \
    float2 v2 = sraw[bi][S][xr][xx + 2];                                        \
    float2 v3 = sraw[bi][S][xr][xx + 3];                                        \
    float2 v4 = sraw[bi][S][xr][xx + 4];                                        \
    const float a0 = v0.x + v1.x + v2.x + v3.x + v4.x;                          \
    const float a1 = v0.y + v1.y + v2.y + v3.y + v4.y;                          \
    const float a2 = fmaf(v4.x, v4.x, fmaf(v3.x, v3.x,                          \
                     fmaf(v2.x, v2.x, fmaf(v1.x, v1.x, v0.x * v0.x))));         \
    const float a3 = fmaf(v4.y, v4.y, fmaf(v3.y, v3.y,                          \
                     fmaf(v2.y, v2.y, fmaf(v1.y, v1.y, v0.y * v0.y))));         \
    const float a4 = fmaf(v4.x, v4.y, fmaf(v3.x, v3.y,                          \
                     fmaf(v2.x, v2.y, fmaf(v1.x, v1.y, v0.x * v0.y))));         \
    SI  += a0 - r0[SLOT]; r0[SLOT] = a0;                                        \
    SJ  += a1 - r1[SLOT]; r1[SLOT] = a1;                                        \
    SII += a2 - r2[SLOT]; r2[SLOT] = a2;                                        \
    SJJ += a3 - r3[SLOT]; r3[SLOT] = a3;                                        \
    SIJ += a4 - r4[SLOT]; r4[SLOT] = a4;                                        \
    zs4[bi][S][xr][xx] = make_float4(SI, SJ, SII, SJJ);                         \
    zs1[bi][S][xr][xx] = SIJ;                                                   \
} while (0)

// One phase = two z-slices, one barrier. SA/SB/DOY compile-time literals.
#define PHASE(SA, SB, DOY) do {                                                 \
    {   /* async fill of pair bi^1 with slices (zpre, zpre+1), zfill OOB */     \
        const bool zA = (zpre < DD), zB = (zpre + 1 < DD);                      \
        const unsigned dA0 = raw_u32 + (bi ^ 1) * RAW_PAIR_BYTES + e0off;       \
        const unsigned dB0 = dA0 + RAW_SLICE_BYTES;                             \
        const float* sI0 = gI + pB0 + preoff;                                   \
        const float* sJ0 = gJ + pB0 + preoff;                                   \
        cpa4(dA0,     sI0,      zA && ok0);                                     \
        cpa4(dA0 + 4, sJ0,      zA && ok0);                                     \
        cpa4(dB0,     sI0 + HW, zB && ok0);                                     \
        cpa4(dB0 + 4, sJ0 + HW, zB && ok0);                                     \
        if (has1) {                                                             \
            const unsigned dA1 = raw_u32 + (bi ^ 1) * RAW_PAIR_BYTES + e1off;   \
            const unsigned dB1 = dA1 + RAW_SLICE_BYTES;                         \
            const float* sI1 = gI + pB1 + preoff;                               \
            const float* sJ1 = gJ + pB1 + preoff;                               \
            cpa4(dA1,     sI1,      zA && ok1);                                 \
            cpa4(dA1 + 4, sJ1,      zA && ok1);                                 \
            cpa4(dB1,     sI1 + HW, zB && ok1);                                 \
            cpa4(dB1 + 4, sJ1 + HW, zB && ok1);                                 \
        }                                                                       \
    }                                                                           \
    float w0 = 0.f, w1 = 0.f;                                                   \
    if (DOY && emit_ok) { w0 = gW[woff]; w1 = gW[woff + WW]; }                  \
    XR(SA, 0);                                                                  \
    XR(SB, 1);                                                                  \
    cpa_wait_all();                                                             \
    __syncthreads();                                                            \
    if (DOY && emit_ok) {                                                       \
        float4 sA = make_float4(0.f, 0.f, 0.f, 0.f);                            \
        float4 sB = make_float4(0.f, 0.f, 0.f, 0.f);                            \
        float sA1 = 0.f, sB1 = 0.f;                                             \
        _Pragma("unroll")                                                       \
        for (int j = 0; j < 6; ++j) {                                           \
            float4 v = zs4[bi][esl][yb + j][exx];                               \
            float  u = zs1[bi][esl][yb + j][exx];                               \
            if (j < 5) { sA.x += v.x; sA.y += v.y; sA.z += v.z; sA.w += v.w;    \
                         sA1 += u; }                                            \
            if (j > 0) { sB.x += v.x; sB.y += v.y; sB.z += v.z; sB.w += v.w;    \
                         sB1 += u; }                                            \
        }                                                                       \
        acc = fmaf(ncc_cc(sA, sA1), w0, acc);                                   \
        acc = fmaf(ncc_cc(sB, sB1), w1, acc);                                   \
        woff += 2 * HW;                                                         \
    }                                                                           \
    bi ^= 1; zpre += 2; preoff += 2 * HW;                                       \
} while (0)

__global__ __launch_bounds__(NT, 2)
void ncc_fused(const float* __restrict__ gI,
               const float* __restrict__ gJ,
               const float* __restrict__ gW,
               float* __restrict__ out)
{
    extern __shared__ unsigned char dsm[];
    float2 (*sraw)[2][RR][RCOLS] = (float2 (*)[2][RR][RCOLS])(dsm + OFF_RAW);
    float4 (*zs4)[2][RR][TX]     = (float4 (*)[2][RR][TX])(dsm + OFF_ZS4);
    float  (*zs1)[2][RR][TX]     = (float  (*)[2][RR][TX])(dsm + OFF_ZS1);
    double* sred  = (double*)(dsm + OFF_SRED);
    int*    slast = (int*)(dsm + OFF_LAST);

    const int tid  = threadIdx.x;
    const int lane = tid & 31;
    const int warp = tid >> 5;

    // ---- block schedule decode: 888 blocks over 224 (x,y,b) columns ----
    // blocks 0..23  : 8 special columns x 3 chunks, z0={0,60,110}, len={60,50,50}
    // blocks 24..887: 216 regular columns x 4 chunks of len 40
    const int bid = blockIdx.x;
    int c, z0, ngrp;                      // ngrp = npairs/5
    if (bid < 24) {
        c = bid / 3;
        const int ci = bid - c * 3;
        z0   = (ci == 0) ? 0 : (ci == 1 ? 60 : 110);
        ngrp = (ci == 0) ? 6 : 5;         // 30 / 25 / 25 pairs
    } else {
        const int q = bid - 24;
        c = 8 + (q >> 2);
        const int ci = q & 3;
        z0 = ci * 40;
        ngrp = 4;                         // 20 pairs
    }
    const int b  = c / (GX * GY);
    const int rr = c - b * (GX * GY);
    const int yt = rr / GX;
    const int xt = rr - yt * GX;
    const int x0 = xt * TX;
    const int y0 = yt * TY;
    const int base = b * (DD * HW);

    // shared-state u32 base for cp.async destinations
    unsigned raw_u32;
    {
        unsigned long long p = (unsigned long long)__cvta_generic_to_shared(dsm + OFF_RAW);
        raw_u32 = (unsigned)p;
    }

    // ---- raw loader mapping: 576 entries over 512 threads ----
    const int row0 = tid / RCOLS, col0 = tid - row0 * RCOLS;
    const int gy0 = y0 + row0 - 2, gx0 = x0 + col0 - 2;
    const bool ok0 = ((unsigned)gy0 < HH) && ((unsigned)gx0 < WW);
    const int pB0 = base + (ok0 ? gy0 * WW + gx0 : 0);
    const unsigned e0off = (unsigned)(row0 * RCOLS + col0) * 8u;

    const bool has1 = (tid < RR * RCOLS - NT);    // 64 extra entries
    const int e1 = tid + NT;
    const int row1 = e1 / RCOLS, col1 = e1 - row1 * RCOLS;
    const int gy1 = y0 + row1 - 2, gx1 = x0 + col1 - 2;
    const bool ok1 = ((unsigned)gy1 < HH) && ((unsigned)gx1 < WW);
    const int pB1 = base + (ok1 ? gy1 * WW + gx1 : 0);
    const unsigned e1off = (unsigned)(row1 * RCOLS + col1) * 8u;

    // ---- xsum entry: one (row, x) per thread ----
    const int xr = warp;            // 0..15
    const int xx = lane;            // 0..31

    // ---- y-emit mapping: 384 threads, 2 slices x 192 ----
    const bool emit_ok = (tid < 384);
    const int esl = tid / 192;                 // slice of the pair
    const int eu  = tid - esl * 192;
    const int exx = eu & 31;
    const int yb  = (eu >> 5) * 2;             // 0,2,..,10
    int woff = base + (z0 + esl) * HW + (y0 + yb) * WW + (x0 + exx);

    // ---- z ring (static slots) + running sums ----
    float r0[5] = {0,0,0,0,0}, r1[5] = {0,0,0,0,0}, r2[5] = {0,0,0,0,0};
    float r3[5] = {0,0,0,0,0}, r4[5] = {0,0,0,0,0};
    float SI = 0.f, SJ = 0.f, SII = 0.f, SJJ = 0.f, SIJ = 0.f;
    float acc = 0.f;

    // ---- prologue: slices z0-2, z0-1 into pair 0 (async + wait + barrier) ----
    {
        const int zp = z0 - 2;
        const bool zA = (zp >= 0);                 // zp+1 >= 0 always (z0 >= 0 -> zp+1 >= -1; z0=0 -> zp+1=-1)
        const bool zB = (zp + 1 >= 0);
        const unsigned dA0 = raw_u32 + e0off;
        const unsigned dB0 = dA0 + RAW_SLICE_BYTES;
        const float* sI0 = gI + pB0 + zp * HW;
        const float* sJ0 = gJ + pB0 + zp * HW;
        cpa4(dA0,     sI0,      zA && ok0);
        cpa4(dA0 + 4, sJ0,      zA && ok0);
        cpa4(dB0,     sI0 + HW, zB && ok0);
        cpa4(dB0 + 4, sJ0 + HW, zB && ok0);
        if (has1) {
            const unsigned dA1 = raw_u32 + e1off;
            const unsigned dB1 = dA1 + RAW_SLICE_BYTES;
            const float* sI1 = gI + pB1 + zp * HW;
            const float* sJ1 = gJ + pB1 + zp * HW;
            cpa4(dA1,     sI1,      zA && ok1);
            cpa4(dA1 + 4, sJ1,      zA && ok1);
            cpa4(dB1,     sI1 + HW, zB && ok1);
            cpa4(dB1 + 4, sJ1 + HW, zB && ok1);
        }
        cpa_wait_all();
        __syncthreads();
    }

    int bi = 0;
    int zpre = z0;               // phase p prefetches slices z0+2p, z0+2p+1
    int preoff = z0 * HW;

    PHASE(0, 1, false);          // XR z0-2, z0-1
    PHASE(2, 3, false);          // XR z0,   z0+1

    // ---- main: ngrp statically-unrolled 5-phase groups (period = 10 slices) ----
#pragma unroll 1
    for (int g = 0; g < ngrp; ++g) {
        PHASE(4, 0, true);
        PHASE(1, 2, true);
        PHASE(3, 4, true);
        PHASE(0, 1, true);
        PHASE(2, 3, true);
    }

    // ---- reduction: shuffle tree (deterministic) ----
    double a = (double)acc;
#pragma unroll
    for (int off = 16; off > 0; off >>= 1)
        a += __shfl_down_sync(0xffffffffu, a, off);
    if (lane == 0) sred[warp] = a;
    __syncthreads();
    if (warp == 0) {
        double s = (lane < 16) ? sred[lane] : 0.0;
#pragma unroll
        for (int off = 8; off > 0; off >>= 1)
            s += __shfl_down_sync(0xffffffffu, s, off);
        if (lane == 0) {
            g_partials[bid] = s;
            __threadfence();
            const unsigned v = atomicAdd(&g_count, 1u);
            *slast = (v == NBLOCKS - 1);
        }
    }
    __syncthreads();

    // ---- last block folds all partials in fixed order ----
    if (*slast) {
        double s = 0.0;
        for (int i = tid; i < NBLOCKS; i += NT) s += g_partials[i];
#pragma unroll
        for (int off = 16; off > 0; off >>= 1)
            s += __shfl_down_sync(0xffffffffu, s, off);
        if (lane == 0) sred[warp] = s;
        __syncthreads();
        if (warp == 0) {
            double t = (lane < 16) ? sred[lane] : 0.0;
#pragma unroll
            for (int off = 8; off > 0; off >>= 1)
                t += __shfl_down_sync(0xffffffffu, t, off);
            if (lane == 0) {
                out[0] = (float)(-t / NTOT);
                g_count = 0;   // reset for next graph replay
            }
        }
    }
}

extern "C" void kernel_launch(void* const* d_in, const int* in_sizes, int n_in,
                              void* d_out, int out_size)
{
    const float* I  = (const float*)d_in[0];
    const float* J  = (const float*)d_in[1];
    const float* Wt = (const float*)d_in[2];
    float* out = (float*)d_out;

    cudaFuncSetAttribute(ncc_fused, cudaFuncAttributeMaxDynamicSharedMemorySize,
                         SMEM_BYTES);
    ncc_fused<<<NBLOCKS, NT, SMEM_BYTES>>>(I, J, Wt, out);
}